// round 5
// baseline (speedup 1.0000x reference)
#include <cuda_runtime.h>

constexpr int NB = 4;
constexpr int C  = 32;
constexpr int H  = 512;
constexpr int W  = 960;
constexpr int Ht = 128;
constexpr int Wt = 240;
constexpr int HW = H * W;
constexpr int BX = 160;     // 960 = 6*160
constexpr int UB = 2;       // channel batch

__global__ __launch_bounds__(BX)
void tile_warp_cost_kernel(const float* __restrict__ tile_plane,
                           const float* __restrict__ fea_l,
                           const float* __restrict__ fea_r,
                           float* __restrict__ out)
{
    const int x = blockIdx.x * BX + threadIdx.x;   // 0..959
    const int y = blockIdx.y;                      // 0..511
    const int b = blockIdx.z;                      // 0..3

    const int ty = y >> 2, tx = x >> 2;
    const int iy = y & 3,  jx = x & 3;

    // tile_plane [B, 3, Ht, Wt]
    const int tbase = b * 3 * Ht * Wt + ty * Wt + tx;
    const float d   = __ldg(tile_plane + tbase);
    const float ddx = __ldg(tile_plane + tbase + Ht * Wt);
    const float ddy = __ldg(tile_plane + tbase + 2 * Ht * Wt);

    // disp_d = 0 slanted-plane disparity; all 3 hypotheses share the frac weight
    const float disp0 = d + ((float)iy - 1.5f) * ddy + ((float)jx - 1.5f) * ddx;
    const float xs0   = (float)x - disp0;
    const float xf    = floorf(xs0);
    const float w     = xs0 - xf;
    const int   x00   = (int)xf;

    // fast path: all 4 taps (x00-1 .. x00+2) inside the aligned 8-float window
    const int  a4i  = (x00 - 1) & ~3;
    const bool fast = (a4i >= 0) && (a4i + 8 <= W);
    const bool s1   = ((x00 - 1) & 1) != 0;
    const bool s2   = ((x00 - 1) & 2) != 0;

    // clamped taps for the (boundary) slow path
    const int j0 = min(max(x00 - 1, 0), W - 1);
    const int j1 = min(max(x00,     0), W - 1);
    const int j2 = min(max(x00 + 1, 0), W - 1);
    const int j3 = min(max(x00 + 2, 0), W - 1);

    const float* pl = fea_l + (size_t)(b * C * H + y) * W + x;
    const float* pr = fea_r + (size_t)(b * C * H + y) * W;

    float cM = 0.f, c0 = 0.f, cP = 0.f, sA = 0.f;

    #pragma unroll 1
    for (int cb = 0; cb < C; cb += UB) {
        float fl[UB], t0[UB], t1[UB], t2[UB], t3[UB];

        #pragma unroll
        for (int u = 0; u < UB; ++u) {
            const float* rr = pr + u * HW;
            fl[u] = __ldg(pl + u * HW);
            if (fast) {
                const float4 fa = __ldg((const float4*)(rr + a4i));
                const float4 fb = __ldg((const float4*)(rr + a4i + 4));
                // shift-by-2 stage (need elements 0..4 after shift)
                const float a0 = s2 ? fa.z : fa.x;
                const float a1 = s2 ? fa.w : fa.y;
                const float a2 = s2 ? fb.x : fa.z;
                const float a3 = s2 ? fb.y : fa.w;
                const float a4 = s2 ? fb.z : fb.x;
                // shift-by-1 stage -> taps
                t0[u] = s1 ? a1 : a0;
                t1[u] = s1 ? a2 : a1;
                t2[u] = s1 ? a3 : a2;
                t3[u] = s1 ? a4 : a3;
            } else {
                t0[u] = __ldg(rr + j0);
                t1[u] = __ldg(rr + j1);
                t2[u] = __ldg(rr + j2);
                t3[u] = __ldg(rr + j3);
            }
        }

        #pragma unroll
        for (int u = 0; u < UB; ++u) {
            const float wP = fmaf(w, t1[u] - t0[u], t0[u]);  // disp_d = +1
            const float w0 = fmaf(w, t2[u] - t1[u], t1[u]);  // disp_d =  0
            const float wM = fmaf(w, t3[u] - t2[u], t2[u]);  // disp_d = -1
            cM += fabsf(fl[u] - wM);
            c0 += fabsf(fl[u] - w0);
            cP += fabsf(fl[u] - wP);
            sA += fabsf(fl[u]);                              // invalid-hyp fallback
        }
        pl += UB * HW;
        pr += UB * HW;
    }

    // per-pixel validity applied once at the end
    const float wm1 = (float)(W - 1);
    if (!((xs0 + 1.0f >= 0.0f) && (xs0 + 1.0f <= wm1))) cM = sA;  // disp_d = -1
    if (!((xs0        >= 0.0f) && (xs0        <= wm1))) c0 = sA;  // disp_d =  0
    if (!((xs0 - 1.0f >= 0.0f) && (xs0 - 1.0f <= wm1))) cP = sA;  // disp_d = +1

    // output [B, 48, Ht, Wt]; channel = vblock*16 + iy*4 + jx; vblocks: -1, 0, +1
    const int chsp  = (iy * 4 + jx) * (Ht * Wt);
    const int obase = b * 48 * Ht * Wt + ty * Wt + tx;
    out[obase + chsp]                = cM;
    out[obase + 16 * Ht * Wt + chsp] = c0;
    out[obase + 32 * Ht * Wt + chsp] = cP;
}

extern "C" void kernel_launch(void* const* d_in, const int* in_sizes, int n_in,
                              void* d_out, int out_size)
{
    const float* tile_plane = (const float*)d_in[0];
    const float* fea_l      = (const float*)d_in[1];
    const float* fea_r      = (const float*)d_in[2];
    float*       out        = (float*)d_out;

    dim3 grid(W / BX, H, NB);   // (6, 512, 4)
    dim3 block(BX);
    tile_warp_cost_kernel<<<grid, block>>>(tile_plane, fea_l, fea_r, out);
}

// round 6
// speedup vs baseline: 1.6298x; 1.6298x over previous
#include <cuda_runtime.h>

constexpr int NB = 4;
constexpr int C  = 32;
constexpr int H  = 512;
constexpr int W  = 960;
constexpr int Ht = 128;
constexpr int Wt = 240;
constexpr int HW = H * W;
constexpr int BX = 160;     // 960 = 6*160
constexpr int UB = 2;       // channel batch

__global__ __launch_bounds__(BX)
void tile_warp_cost_kernel(const float* __restrict__ tile_plane,
                           const float* __restrict__ fea_l,
                           const float* __restrict__ fea_r,
                           float* __restrict__ out)
{
    const int x = blockIdx.x * BX + threadIdx.x;   // 0..959
    const int y = blockIdx.y;                      // 0..511
    const int b = blockIdx.z;                      // 0..3

    const int lane = threadIdx.x & 31;
    const int tl   = lane >> 2;                    // tile index within warp (0..7)
    const int tp   = lane & 3;                     // position within tile

    const int ty = y >> 2, tx = x >> 2;
    const int iy = y & 3,  jx = x & 3;

    // tile_plane [B, 3, Ht, Wt]
    const int tbase = b * 3 * Ht * Wt + ty * Wt + tx;
    const float d   = __ldg(tile_plane + tbase);
    const float ddx = __ldg(tile_plane + tbase + Ht * Wt);
    const float ddy = __ldg(tile_plane + tbase + 2 * Ht * Wt);

    const float disp0 = d + ((float)iy - 1.5f) * ddy + ((float)jx - 1.5f) * ddx;
    const float xs0   = (float)x - disp0;
    const float xf    = floorf(xs0);
    const float w     = xs0 - xf;
    const int   x00   = (int)xf;

    // ---- tile-cooperative window: min/max of x00 over the 4 tile lanes ----
    int mn = x00, mx = x00;
    mn = min(mn, __shfl_xor_sync(0xffffffffu, mn, 1));
    mx = max(mx, __shfl_xor_sync(0xffffffffu, mx, 1));
    mn = min(mn, __shfl_xor_sync(0xffffffffu, mn, 2));
    mx = max(mx, __shfl_xor_sync(0xffffffffu, mx, 2));

    const int  tb    = (mn - 1) & ~1;              // even-aligned window base (tile-uniform)
    const bool fastp = (tb >= 0) && (tb + 8 <= W) && (mx + 2 <= tb + 7);
    const unsigned fmask = __ballot_sync(0xffffffffu, fastp);

    // fast path: tap k sits at window pos q+k; window held as float2 per lane
    const int  q    = x00 - 1 - tb;                // 0..4 when fastp
    const bool qodd = (q & 1) != 0;
    const int  sA   = (tl << 2) + ((q + 1) >> 1);  // shfl src for r0 taps
    const int  sB   = (tl << 2) + (q >> 1);        // shfl src for r1 taps
    const int  goff = tb + 2 * tp;                 // this lane's float2 within window

    // slow path: exact clamped taps
    const int j0 = min(max(x00 - 1, 0), W - 1);
    const int j1 = min(max(x00,     0), W - 1);
    const int j2 = min(max(x00 + 1, 0), W - 1);
    const int j3 = min(max(x00 + 2, 0), W - 1);

    const float* pl = fea_l + (size_t)(b * C * H + y) * W + x;
    const float* pr = fea_r + (size_t)(b * C * H + y) * W;

    float cM = 0.f, c0 = 0.f, cP = 0.f, sA_acc = 0.f;

    #pragma unroll 1
    for (int cb = 0; cb < C; cb += UB) {
        float fl[UB], t0[UB], t1[UB], t2[UB], t3[UB];
        float r0[UB], r1[UB];

        // load phase
        #pragma unroll
        for (int u = 0; u < UB; ++u) {
            const float* rr = pr + u * HW;
            fl[u] = __ldg(pl + u * HW);
            if (fastp) {
                const float2 v = __ldg((const float2*)(rr + goff));
                r0[u] = v.x; r1[u] = v.y;
            } else {
                t0[u] = __ldg(rr + j0);
                t1[u] = __ldg(rr + j1);
                t2[u] = __ldg(rr + j2);
                t3[u] = __ldg(rr + j3);
            }
        }

        // redistribute taps within tile via shuffle (fast lanes only)
        if (fastp) {
            #pragma unroll
            for (int u = 0; u < UB; ++u) {
                const float A  = __shfl_sync(fmask, r0[u], sA);
                const float Bv = __shfl_sync(fmask, r0[u], sA + 1);
                const float Cv = __shfl_sync(fmask, r1[u], sB);
                const float Dv = __shfl_sync(fmask, r1[u], sB + 1);
                t0[u] = qodd ? Cv : A;
                t1[u] = qodd ? A  : Cv;
                t2[u] = qodd ? Dv : Bv;
                t3[u] = qodd ? Bv : Dv;
            }
        }

        // compute phase
        #pragma unroll
        for (int u = 0; u < UB; ++u) {
            const float wP = fmaf(w, t1[u] - t0[u], t0[u]);  // disp_d = +1
            const float w0 = fmaf(w, t2[u] - t1[u], t1[u]);  // disp_d =  0
            const float wM = fmaf(w, t3[u] - t2[u], t2[u]);  // disp_d = -1
            cM += fabsf(fl[u] - wM);
            c0 += fabsf(fl[u] - w0);
            cP += fabsf(fl[u] - wP);
            sA_acc += fabsf(fl[u]);                          // invalid-hyp fallback
        }
        pl += UB * HW;
        pr += UB * HW;
    }

    // per-pixel validity applied once at the end
    const float wm1 = (float)(W - 1);
    if (!((xs0 + 1.0f >= 0.0f) && (xs0 + 1.0f <= wm1))) cM = sA_acc;  // disp_d = -1
    if (!((xs0        >= 0.0f) && (xs0        <= wm1))) c0 = sA_acc;  // disp_d =  0
    if (!((xs0 - 1.0f >= 0.0f) && (xs0 - 1.0f <= wm1))) cP = sA_acc;  // disp_d = +1

    // output [B, 48, Ht, Wt]; channel = vblock*16 + iy*4 + jx; vblocks: -1, 0, +1
    const int chsp  = (iy * 4 + jx) * (Ht * Wt);
    const int obase = b * 48 * Ht * Wt + ty * Wt + tx;
    out[obase + chsp]                = cM;
    out[obase + 16 * Ht * Wt + chsp] = c0;
    out[obase + 32 * Ht * Wt + chsp] = cP;
}

extern "C" void kernel_launch(void* const* d_in, const int* in_sizes, int n_in,
                              void* d_out, int out_size)
{
    const float* tile_plane = (const float*)d_in[0];
    const float* fea_l      = (const float*)d_in[1];
    const float* fea_r      = (const float*)d_in[2];
    float*       out        = (float*)d_out;

    dim3 grid(W / BX, H, NB);   // (6, 512, 4)
    dim3 block(BX);
    tile_warp_cost_kernel<<<grid, block>>>(tile_plane, fea_l, fea_r, out);
}